// round 15
// baseline (speedup 1.0000x reference)
#include <cuda_runtime.h>
#include <cuda_fp16.h>
#include <cuda_bf16.h>
#include <math.h>

#define BB 64
#define TT 512
#define NN 256
#define DD 128
#define LOG_2PI_F 1.8378770664093453f
#define LN2_F 0.6931471805599453f

#define CH 128           // chunk length (TT / K, K = 4)
#define WU 24            // warm-up steps; multiple of 4 (renorm alignment)

// ---------------- device scratch (static globals; no allocs) ----------------
static __device__ float          E_sc[BB * TT * NN];   // emission logprobs [B*T, N] fp32
static __device__ float          M_sc[BB * TT];        // per-row max of E
static __device__ __nv_bfloat162 AhT_g[(NN / 2) * NN]; // packed A^T bf16
static __device__ __half2        WpT_g[DD * NN];       // [d][n] = (-0.5*iv, mu*iv) as half2
static __device__ float          cvec_g[NN];
static __device__ float          logpi_g[NN];
static __device__ float          logprop4_g[4 * BB];   // per-chunk contributions

// order-preserving float<->uint map for REDUX-based fp max (handles negatives)
__device__ __forceinline__ float warp_max_f(float x) {
    unsigned u = __float_as_uint(x);
    u = ((int)u >= 0) ? (u ^ 0x80000000u) : ~u;
    u = __reduce_max_sync(0xffffffffu, u);
    return ((int)u < 0) ? __uint_as_float(u ^ 0x80000000u) : __uint_as_float(~u);
}

// ---------------- merged prep kernel (unchanged, proven) ----------------
__global__ void prep_all(const float* __restrict__ trans, const float* __restrict__ pri,
                         const float* __restrict__ mu, const float* __restrict__ lv) {
    __shared__ float redA[8], redB[8];
    int bid = blockIdx.x, t = threadIdx.x;
    int wid = t >> 5, lane = t & 31;

    if (bid < 128) {
        int k = bid;
        float v0 = trans[(2 * k) * NN + t];
        float v1 = trans[(2 * k + 1) * NN + t];
        float m0 = v0, m1 = v1;
#pragma unroll
        for (int o = 16; o; o >>= 1) {
            m0 = fmaxf(m0, __shfl_xor_sync(0xffffffffu, m0, o));
            m1 = fmaxf(m1, __shfl_xor_sync(0xffffffffu, m1, o));
        }
        if (lane == 0) { redA[wid] = m0; redB[wid] = m1; }
        __syncthreads();
        float mb0 = redA[0], mb1 = redB[0];
#pragma unroll
        for (int w = 1; w < 8; w++) { mb0 = fmaxf(mb0, redA[w]); mb1 = fmaxf(mb1, redB[w]); }
        __syncthreads();
        float e0 = expf(v0 - mb0), e1 = expf(v1 - mb1);
        float s0 = e0, s1 = e1;
#pragma unroll
        for (int o = 16; o; o >>= 1) {
            s0 += __shfl_xor_sync(0xffffffffu, s0, o);
            s1 += __shfl_xor_sync(0xffffffffu, s1, o);
        }
        if (lane == 0) { redA[wid] = s0; redB[wid] = s1; }
        __syncthreads();
        float S0 = 0.f, S1 = 0.f;
#pragma unroll
        for (int w = 0; w < 8; w++) { S0 += redA[w]; S1 += redB[w]; }
        AhT_g[k * NN + t] = __floats2bfloat162_rn(e0 / S0, e1 / S1);
    } else if (bid == 128) {
        float v = pri[t];
        float m = v;
#pragma unroll
        for (int o = 16; o; o >>= 1) m = fmaxf(m, __shfl_xor_sync(0xffffffffu, m, o));
        if (lane == 0) redA[wid] = m;
        __syncthreads();
        float mb = redA[0];
#pragma unroll
        for (int w = 1; w < 8; w++) mb = fmaxf(mb, redA[w]);
        __syncthreads();
        float e = expf(v - mb);
        float s = e;
#pragma unroll
        for (int o = 16; o; o >>= 1) s += __shfl_xor_sync(0xffffffffu, s, o);
        if (lane == 0) redA[wid] = s;
        __syncthreads();
        float S = 0.f;
#pragma unroll
        for (int w = 0; w < 8; w++) S += redA[w];
        logpi_g[t] = (v - mb) - logf(S);
    } else {
        int wb = bid - 129;
        int n = 2 * wb + (t >> 7);
        int d = t & 127;
        float l = lv[n * DD + d];
        float m = mu[n * DD + d];
        float iv = expf(-l);
        WpT_g[d * NN + n] = __floats2half2_rn(-0.5f * iv, m * iv);
        float c = m * m * iv + l + LOG_2PI_F;
#pragma unroll
        for (int o = 16; o; o >>= 1) c += __shfl_xor_sync(0xffffffffu, c, o);
        if (lane == 0) redA[wid] = c;
        __syncthreads();
        if ((t & 127) == 0) {
            int base = (t >> 7) * 4;
            float s = redA[base] + redA[base + 1] + redA[base + 2] + redA[base + 3];
            cvec_g[n] = -0.5f * s;
        }
    }
}

// ---------------- emission GEMM + row-max epilogue (unchanged, at HFMA2 peak) --------
__global__ void __launch_bounds__(256, 1) emis_kernel(const float* __restrict__ X) {
    __shared__ __align__(16) __half2 xp[32 * DD];
    __shared__ __align__(16) float redM[32][8];
    int tid = threadIdx.x;
    int r0 = blockIdx.x * 32;
    int ib = tid & 1, nb = tid >> 1;
    int wid = tid >> 5, lane = tid & 31;

#pragma unroll
    for (int it = 0; it < 16; it++) {
        int idx = it * 256 + tid;
        int m = idx >> 7, d = idx & 127;
        float x = X[(r0 + m) * DD + d];
        xp[idx] = __floats2half2_rn(x * x, x);
    }

    __half2 w0[64], w1[64];
#pragma unroll
    for (int k = 0; k < 64; k++) {
        w0[k] = WpT_g[(64 * ib + k) * NN + 2 * nb];
        w1[k] = WpT_g[(64 * ib + k) * NN + 2 * nb + 1];
    }
    float cn = cvec_g[tid];
    __syncthreads();

    for (int m = 0; m < 32; m++) {
        const float4* xr = reinterpret_cast<const float4*>(xp + m * DD + 64 * ib);
        __half2 c0a = __float2half2_rn(0.f), c0b = c0a, c1a = c0a, c1b = c0a;
#pragma unroll
        for (int q = 0; q < 16; q++) {
            float4 v = xr[q];
            const __half2* xv = reinterpret_cast<const __half2*>(&v);
            c0a = __hfma2(w0[4 * q + 0], xv[0], c0a);
            c1a = __hfma2(w1[4 * q + 0], xv[0], c1a);
            c0b = __hfma2(w0[4 * q + 1], xv[1], c0b);
            c1b = __hfma2(w1[4 * q + 1], xv[1], c1b);
            c0a = __hfma2(w0[4 * q + 2], xv[2], c0a);
            c1a = __hfma2(w1[4 * q + 2], xv[2], c1a);
            c0b = __hfma2(w0[4 * q + 3], xv[3], c0b);
            c1b = __hfma2(w1[4 * q + 3], xv[3], c1b);
        }
        float2 f0 = __half22float2(__hadd2(c0a, c0b));
        float2 f1 = __half22float2(__hadd2(c1a, c1b));
        float S0 = f0.x + f0.y, S1 = f1.x + f1.y;
        S0 += __shfl_xor_sync(0xffffffffu, S0, 1);
        S1 += __shfl_xor_sync(0xffffffffu, S1, 1);
        float val = (ib ? S1 : S0) + cn;
        E_sc[(r0 + m) * NN + tid] = val;
        float mm = warp_max_f(val);
        if (lane == 0) redM[m][wid] = mm;
    }
    __syncthreads();
    if (tid < 32) {
        float4 q0 = *reinterpret_cast<const float4*>(&redM[tid][0]);
        float4 q1 = *reinterpret_cast<const float4*>(&redM[tid][4]);
        float M = fmaxf(fmaxf(fmaxf(q0.x, q0.y), fmaxf(q0.z, q0.w)),
                        fmaxf(fmaxf(q1.x, q1.y), fmaxf(q1.z, q1.w)));
        M_sc[r0 + tid] = M;
    }
}

// ---------------- one recursion step (inlined; A tile shared by reference) ----------
__device__ __forceinline__ float matvec_half(
    const __nv_bfloat162 (&a0)[64], const __nv_bfloat162 (&a1)[64],
    const __nv_bfloat16* psm_part, int ib)
{
    const float4* p4 = reinterpret_cast<const float4*>(psm_part);
    __nv_bfloat162 bz = __float2bfloat162_rn(0.f);
    __nv_bfloat162 c0a = bz, c0b = bz, c1a = bz, c1b = bz;
#pragma unroll
    for (int q = 0; q < 16; q++) {
        float4 v = p4[q];
        const __nv_bfloat162* pv = reinterpret_cast<const __nv_bfloat162*>(&v);
        c0a = __hfma2(a0[4 * q + 0], pv[0], c0a);
        c1a = __hfma2(a1[4 * q + 0], pv[0], c1a);
        c0b = __hfma2(a0[4 * q + 1], pv[1], c0b);
        c1b = __hfma2(a1[4 * q + 1], pv[1], c1b);
        c0a = __hfma2(a0[4 * q + 2], pv[2], c0a);
        c1a = __hfma2(a1[4 * q + 2], pv[2], c1a);
        c0b = __hfma2(a0[4 * q + 3], pv[3], c0b);
        c1b = __hfma2(a1[4 * q + 3], pv[3], c1b);
    }
    float2 f0 = __bfloat1622float2(__hadd2(c0a, c0b));
    float2 f1 = __bfloat1622float2(__hadd2(c1a, c1b));
    float S0 = f0.x + f0.y, S1 = f1.x + f1.y;
    S0 += __shfl_xor_sync(0xffffffffu, S0, 1);
    S1 += __shfl_xor_sync(0xffffffffu, S1, 1);
    return ib ? S1 : S0;
}

// All conditions below are uniform across the CTA (safe around sync intrinsics).
__device__ __forceinline__ void rec_step(
    int s, int t_init, int t_end, bool has_warm, int t_rec,
    const float* Erow, const float* Mrow,
    const __nv_bfloat162 (&a0)[64], const __nv_bfloat162 (&a1)[64],
    __nv_bfloat16* psmb, unsigned* redu, float* redV,
    int cur, int tid, int ib, int lane, int wid,
    float& p, float& mhat, float& e_next, float& Mn, float& V1)
{
    int t = t_init + s;
    if (t >= t_end) return;                              // uniform predicate
    float e = e_next, Mt = Mn;
    if (t + 1 < t_end) { e_next = Erow[(t + 1) * NN + tid]; Mn = Mrow[t + 1]; }

    // V1 capture: redV staged at end of step t_rec-1, read here (after its barrier)
    if (has_warm && t == t_rec && tid == 0) {
        float tot = redV[0] + redV[1] + redV[2] + redV[3]
                  + redV[4] + redV[5] + redV[6] + redV[7];
        V1 = mhat + __logf(tot);
    }
    // renorm application (staged at t-1 = t_init, t_init+4, ...; t_init % 4 == 0)
    float rescale = 1.0f;
    if (((t - 1) & 3) == 0) {
        unsigned pm = max(max(max(redu[0], redu[1]), max(redu[2], redu[3])),
                          max(max(redu[4], redu[5]), max(redu[6], redu[7])));
        int e2 = (int)(pm >> 23) - 127;
        rescale = __uint_as_float((unsigned)(127 - e2) << 23);   // 2^-e2 (exact)
        mhat += (float)e2 * LN2_F;
    }

    float S = matvec_half(a0, a1, psmb + cur * NN + 128 * ib, ib);
    p = __expf(e - Mt) * S * rescale;
    mhat += Mt;

    if ((t & 3) == 0) {                                  // stage renorm for t+1
        unsigned pb = __reduce_max_sync(0xffffffffu, __float_as_uint(p));
        if (lane == 0) redu[wid] = pb;
    }
    if (has_warm && t == t_rec - 1) {                    // stage boundary sum for V1
        float sv = p;
#pragma unroll
        for (int o = 16; o; o >>= 1) sv += __shfl_xor_sync(0xffffffffu, sv, o);
        if (lane == 0) redV[wid] = sv;
    }
    psmb[(cur ^ 1) * NN + tid] = __float2bfloat16(p);
}

// ---------------- forward recursion: K=4 chunks, 2 recursions per CTA ----------------
// CTA c: b = c & 63, pair = c >> 6. Recursion A = chunk 2*pair, B = chunk 2*pair+1.
// Both share the A-matrix register tile; one barrier per step covers both.
__global__ void __launch_bounds__(256, 1) forward_rec() {
    __shared__ __align__(16) __nv_bfloat16 psmA[2 * NN], psmB[2 * NN];
    __shared__ __align__(16) unsigned reduA[8], reduB[8];
    __shared__ float redVA[8], redVB[8];
    __shared__ float redsA[8], redsB[8];
    int b = blockIdx.x & (BB - 1);
    int pair = blockIdx.x >> 6;                          // 0 or 1
    int qA = 2 * pair, qB = 2 * pair + 1;
    int tid = threadIdx.x;
    int wid = tid >> 5, lane = tid & 31;
    int ib = tid & 1, jb = tid >> 1;

    __nv_bfloat162 a0[64], a1[64];
#pragma unroll
    for (int k = 0; k < 64; k++) {
        a0[k] = AhT_g[(64 * ib + k) * NN + 2 * jb];
        a1[k] = AhT_g[(64 * ib + k) * NN + 2 * jb + 1];
    }

    const float* __restrict__ Erow = E_sc + b * TT * NN;
    const float* __restrict__ Mrow = M_sc + b * TT;

    bool warmA = (qA != 0);
    int tA_init = warmA ? (CH * qA - WU) : 0;
    int tA_end = CH * (qA + 1), tA_rec = CH * qA;
    int tB_init = CH * qB - WU;
    int tB_end = CH * (qB + 1), tB_rec = CH * qB;

    // init recursion A at tA_init
    float MA0 = Mrow[tA_init];
    float plA = Erow[tA_init * NN + tid] - MA0;
    if (!warmA) plA += logpi_g[tid];
    float pA = __expf(plA), mhatA = MA0, V1A = 0.f;
    psmA[tid] = __float2bfloat16(pA);
    {
        unsigned pb = __reduce_max_sync(0xffffffffu, __float_as_uint(pA));
        if (lane == 0) reduA[wid] = pb;
    }
    float enA = Erow[(tA_init + 1) * NN + tid], MnA = Mrow[tA_init + 1];

    // init recursion B at tB_init (always warm/uniform)
    float MB0 = Mrow[tB_init];
    float pB = __expf(Erow[tB_init * NN + tid] - MB0), mhatB = MB0, V1B = 0.f;
    psmB[tid] = __float2bfloat16(pB);
    {
        unsigned pb = __reduce_max_sync(0xffffffffu, __float_as_uint(pB));
        if (lane == 0) reduB[wid] = pb;
    }
    float enB = Erow[(tB_init + 1) * NN + tid], MnB = Mrow[tB_init + 1];

    int cur = 0;
    __syncthreads();

    for (int s = 1; s <= CH + WU - 1; s++) {
        rec_step(s, tA_init, tA_end, warmA, tA_rec, Erow, Mrow, a0, a1,
                 psmA, reduA, redVA, cur, tid, ib, lane, wid,
                 pA, mhatA, enA, MnA, V1A);
        rec_step(s, tB_init, tB_end, true, tB_rec, Erow, Mrow, a0, a1,
                 psmB, reduB, redVB, cur, tid, ib, lane, wid,
                 pB, mhatB, enB, MnB, V1B);
        __syncthreads();                                 // ONE barrier per step
        cur ^= 1;
    }

    // chunk totals
    float sA = pA, sB = pB;
#pragma unroll
    for (int o = 16; o; o >>= 1) {
        sA += __shfl_xor_sync(0xffffffffu, sA, o);
        sB += __shfl_xor_sync(0xffffffffu, sB, o);
    }
    if (lane == 0) { redsA[wid] = sA; redsB[wid] = sB; }
    __syncthreads();
    if (tid == 0) {
        float totA = 0.f, totB = 0.f;
#pragma unroll
        for (int w = 0; w < 8; w++) { totA += redsA[w]; totB += redsB[w]; }
        float LA = mhatA + __logf(totA);
        if (warmA) LA -= V1A;
        float LB = mhatB + __logf(totB) - V1B;
        logprop4_g[qA * BB + b] = LA;
        logprop4_g[qB * BB + b] = LB;
    }
}

// ---------------- final: sum all 4 chunk contributions over batch ----------------
__global__ void finalize_kernel(float* __restrict__ out) {
    __shared__ float red[2];
    int t = threadIdx.x;
    float v = logprop4_g[t] + logprop4_g[BB + t]
            + logprop4_g[2 * BB + t] + logprop4_g[3 * BB + t];
#pragma unroll
    for (int o = 16; o; o >>= 1) v += __shfl_xor_sync(0xffffffffu, v, o);
    if ((t & 31) == 0) red[t >> 5] = v;
    __syncthreads();
    if (t == 0) out[0] = red[0] + red[1];
}

// ---------------- launch ----------------
extern "C" void kernel_launch(void* const* d_in, const int* in_sizes, int n_in,
                              void* d_out, int out_size) {
    (void)in_sizes; (void)n_in; (void)out_size;
    const float* X     = (const float*)d_in[0];
    const float* mu    = (const float*)d_in[1];
    const float* lv    = (const float*)d_in[2];
    const float* trans = (const float*)d_in[3];
    const float* pri   = (const float*)d_in[4];
    float* out = (float*)d_out;

    prep_all<<<257, 256>>>(trans, pri, mu, lv);
    emis_kernel<<<(BB * TT) / 32, 256>>>(X);
    forward_rec<<<2 * BB, 256>>>();
    finalize_kernel<<<1, 64>>>(out);
}